// round 1
// baseline (speedup 1.0000x reference)
#include <cuda_runtime.h>
#include <math.h>

// ---------------- constants ----------------
#define VOCAB 20000
#define Dd 100
#define Hh 100
#define Kk 3
#define N_NODE 256
#define Rr 8
#define Ss 52
#define SP 50            // S - K + 1
#define Ee 20000
#define NREV 2048        // N_NODE * Rr

// ---------------- device scratch (no allocation allowed) ----------------
__device__ __align__(16) float g_proj[VOCAB * 300];        // [v][k*100+h]  24MB
__device__ __align__(16) float g_P[2 * NREV * Dd];         // [br][node*8+r][d]
__device__ __align__(16) float g_Q[2 * N_NODE * Dd];       // [br][node][d]
__device__ __align__(16) float g_zw[2 * NREV];             // [br][node*8+r]
__device__ __align__(16) float g_pc[2 * NREV];             // [br][node*8+r]
__device__ __align__(16) float g_A[N_NODE * N_NODE * Rr];  // [u][i][r]
__device__ __align__(16) float g_B[N_NODE * N_NODE * Rr];  // [i][u][r]

// ---------------- K1: proj[v][k*100+h] = sum_d emb[v,d] * conv_w[h,0,k,d] ----------------
// grid: 1250 blocks of 16 vocab rows; block: 160 threads; thread handles n0=tid, n1=tid+160.
#define TV 16
__global__ void proj_kernel(const float* __restrict__ emb, const float* __restrict__ convw)
{
    __shared__ float4 esh[TV][25];
    const int v0 = blockIdx.x * TV;
    const int tid = threadIdx.x;

    for (int i = tid; i < TV * 25; i += 160) {
        int v = i / 25, d4 = i % 25;
        esh[v][d4] = reinterpret_cast<const float4*>(emb)[(v0 + v) * 25 + d4];
    }
    __syncthreads();

    const int n0 = tid;
    const int n1 = tid + 160;
    const bool has1 = (n1 < 300);
    const int k0 = n0 / 100, h0 = n0 % 100;
    const int k1 = has1 ? n1 / 100 : 0, h1 = has1 ? n1 % 100 : 0;
    const float4* w0p = reinterpret_cast<const float4*>(convw + h0 * 300 + k0 * 100);
    const float4* w1p = reinterpret_cast<const float4*>(convw + h1 * 300 + k1 * 100);

    float acc0[TV], acc1[TV];
#pragma unroll
    for (int v = 0; v < TV; v++) { acc0[v] = 0.f; acc1[v] = 0.f; }

    for (int d4 = 0; d4 < 25; d4++) {
        float4 w0 = w0p[d4];
        float4 w1 = has1 ? w1p[d4] : make_float4(0.f, 0.f, 0.f, 0.f);
#pragma unroll
        for (int v = 0; v < TV; v++) {
            float4 e = esh[v][d4];
            acc0[v] += e.x * w0.x + e.y * w0.y + e.z * w0.z + e.w * w0.w;
            acc1[v] += e.x * w1.x + e.y * w1.y + e.z * w1.z + e.w * w1.w;
        }
    }
#pragma unroll
    for (int v = 0; v < TV; v++) {
        g_proj[(v0 + v) * 300 + n0] = acc0[v];
        if (has1) g_proj[(v0 + v) * 300 + n1] = acc1[v];
    }
}

// ---------------- K2: per-review: conv-sum + relu, z, cmax, P, zw, pc ----------------
// grid: (2048, 2), block: 128
__global__ void review_kernel(const int* __restrict__ ur, const int* __restrict__ ir,
                              const float* __restrict__ convb,
                              const float* __restrict__ fcw, const float* __restrict__ fcb,
                              const float* __restrict__ w2, const float* __restrict__ w2b,
                              const float* __restrict__ hrw, const float* __restrict__ hcw,
                              float* __restrict__ out)
{
    const int br  = blockIdx.y;        // 0 = user, 1 = item
    const int idx = blockIdx.x;        // node*8 + r
    const int tid = threadIdx.x;
    const int* revs = br ? ir : ur;

    __shared__ int   tok[Ss];
    __shared__ float cb[Hh], fw[Hh];
    __shared__ float c_sh[SP][101];    // padded to kill bank conflicts
    __shared__ float z_sh[SP];
    __shared__ float cmax_sh[Hh];
    __shared__ float P_sh[Hh];

    if (tid < Ss)  tok[tid] = revs[idx * Ss + tid];
    if (tid < Hh)  { cb[tid] = convb[tid]; fw[tid] = fcw[tid]; }
    __syncthreads();

    // conv via precomputed per-token projections
    for (int i = tid; i < SP * Hh; i += 128) {
        int s = i / Hh, h = i - s * Hh;
        float v = cb[h]
                + g_proj[tok[s]     * 300 +        h]
                + g_proj[tok[s + 1] * 300 + 100 + h]
                + g_proj[tok[s + 2] * 300 + 200 + h];
        c_sh[s][h] = fmaxf(v, 0.f);
    }
    __syncthreads();

    // rho -> z (straight-through round == round(sigmoid))
    if (tid < SP) {
        float x = fcb[0];
#pragma unroll 4
        for (int h = 0; h < Hh; h++) x += c_sh[tid][h] * fw[h];
        float rho = 1.f / (1.f + expf(-x));
        float z = rintf(rho);          // round half to even, matches jnp.round
        z_sh[tid] = z;
        out[2 * Ee + br * (NREV * SP) + idx * SP + tid] = z;
    }
    // cmax over positions (c >= 0 after relu, so 0 init is exact)
    if (tid < Hh) {
        float m = 0.f;
#pragma unroll 5
        for (int s = 0; s < SP; s++) m = fmaxf(m, c_sh[s][tid]);
        cmax_sh[tid] = m;
    }
    __syncthreads();

    // P[d] = fc_w2_b[d] + sum_h cmax[h] * fc_w2_w[d,h]
    if (tid < Dd) {
        float p = w2b[tid];
        const float* wr = w2 + tid * Hh;
#pragma unroll 4
        for (int h = 0; h < Hh; h++) p += cmax_sh[h] * wr[h];
        P_sh[tid] = p;
        g_P[(br * NREV + idx) * Dd + tid] = p;
    }
    __syncthreads();

    if (tid == 0) {
        float zw = 0.f;
        for (int s = 0; s < SP; s++) zw += z_sh[s] * hrw[br * SP + s];
        g_zw[br * NREV + idx] = zw;
    }
    if (tid == 32) {
        float pc = 0.f;
        for (int d = 0; d < Dd; d++) pc += P_sh[d] * hcw[br * Dd + d];
        g_pc[br * NREV + idx] = pc;
    }
}

// ---------------- K3: Q[node] = sum_r P[node,r,:] ----------------
// grid: 512 (br*256+node), block: 100
__global__ void qsum_kernel()
{
    const int node = blockIdx.x;
    const int d = threadIdx.x;
    float q = 0.f;
#pragma unroll
    for (int r = 0; r < Rr; r++) q += g_P[(node * Rr + r) * Dd + d];
    g_Q[node * Dd + d] = q;
}

// ---------------- K4: A[u][i][r] = P_u[u,r]·Q_i[i];  B[i][u][r] = P_i[i,r]·Q_u[u] ----------------
// grid: (256, 2), block: 256
__global__ void pair_kernel()
{
    const int pb = blockIdx.y;    // 0 -> A, 1 -> B
    const int a  = blockIdx.x;    // own node
    const int tid = threadIdx.x;  // other node

    __shared__ float4 Pa[Rr][25];
    const float* Pbase = g_P + (pb * NREV + a * Rr) * Dd;
    for (int i = tid; i < Rr * 25; i += 256)
        Pa[i / 25][i % 25] = reinterpret_cast<const float4*>(Pbase)[i];
    __syncthreads();

    const float4* q = reinterpret_cast<const float4*>(g_Q + ((1 - pb) * N_NODE + tid) * Dd);
    float acc[Rr];
#pragma unroll
    for (int r = 0; r < Rr; r++) acc[r] = 0.f;

    for (int d4 = 0; d4 < 25; d4++) {
        float4 qq = q[d4];
#pragma unroll
        for (int r = 0; r < Rr; r++) {
            float4 p = Pa[r][d4];
            acc[r] += p.x * qq.x + p.y * qq.y + p.z * qq.z + p.w * qq.w;
        }
    }
    float* dst = (pb ? g_B : g_A) + (a * N_NODE + tid) * Rr;
    reinterpret_cast<float4*>(dst)[0] = make_float4(acc[0], acc[1], acc[2], acc[3]);
    reinterpret_cast<float4*>(dst)[1] = make_float4(acc[4], acc[5], acc[6], acc[7]);
}

// ---------------- K5: per-edge predictions ----------------
__global__ void edge_kernel(const int* __restrict__ uid, const int* __restrict__ iid,
                            const float* __restrict__ ubias, const float* __restrict__ ibias,
                            const float* __restrict__ gbias, float* __restrict__ out)
{
    const int e = blockIdx.x * 256 + threadIdx.x;
    if (e >= Ee) return;
    const int u = uid[e], i = iid[e];

    const float* A   = g_A + (u * N_NODE + i) * Rr;
    const float* B   = g_B + (i * N_NODE + u) * Rr;
    const float* zwu = g_zw + u * Rr;
    const float* zwi = g_zw + NREV + i * Rr;
    const float* pcu = g_pc + u * Rr;
    const float* pci = g_pc + NREV + i * Rr;

    float pr = ubias[u] + ibias[i] + gbias[0];
    float pc = 0.f;
#pragma unroll
    for (int r = 0; r < Rr; r++) {
        float su = 1.f / (1.f + expf(-A[r]));
        float sv = 1.f / (1.f + expf(-B[r]));
        pr += su * zwu[r] + sv * zwi[r];
        pc += su * pcu[r] + sv * pci[r];
    }
    out[e]      = pr;
    out[Ee + e] = pc;
}

// ---------------- launcher ----------------
extern "C" void kernel_launch(void* const* d_in, const int* in_sizes, int n_in,
                              void* d_out, int out_size)
{
    const int*   user_reviews = (const int*)  d_in[0];
    const int*   item_reviews = (const int*)  d_in[1];
    const int*   uid          = (const int*)  d_in[2];
    const int*   iid          = (const int*)  d_in[3];
    const float* emb_table    = (const float*)d_in[4];
    const float* conv_w       = (const float*)d_in[5];
    const float* conv_b       = (const float*)d_in[6];
    const float* fc_w_w       = (const float*)d_in[7];
    const float* fc_w_b       = (const float*)d_in[8];
    const float* fc_w2_w      = (const float*)d_in[9];
    const float* fc_w2_b      = (const float*)d_in[10];
    const float* h_r_w        = (const float*)d_in[11];
    const float* h_c_w        = (const float*)d_in[12];
    const float* user_bias    = (const float*)d_in[13];
    const float* item_bias    = (const float*)d_in[14];
    const float* global_bias  = (const float*)d_in[15];
    float* out = (float*)d_out;

    proj_kernel<<<VOCAB / TV, 160>>>(emb_table, conv_w);
    review_kernel<<<dim3(NREV, 2), 128>>>(user_reviews, item_reviews,
                                          conv_b, fc_w_w, fc_w_b,
                                          fc_w2_w, fc_w2_b, h_r_w, h_c_w, out);
    qsum_kernel<<<2 * N_NODE, Dd>>>();
    pair_kernel<<<dim3(N_NODE, 2), 256>>>();
    edge_kernel<<<(Ee + 255) / 256, 256>>>(uid, iid, user_bias, item_bias, global_bias, out);
}